// round 1
// baseline (speedup 1.0000x reference)
#include <cuda_runtime.h>
#include <math.h>
#include <stdint.h>

// Problem dims
#define T_DIM 4096
#define B_DIM 512
#define NSTEP 4095            // scan steps (t = 1..4095)
#define NELEM (T_DIM * B_DIM) // 2,097,152 = 2^21
#define PREP_BLOCKS (NELEM / 256) // 8192

// ---------------------------------------------------------------------------
// Device scratch (static: no allocations allowed)
// ---------------------------------------------------------------------------
// Packed per-(step, b) coefficients: 4 x float4 per element.
//   c0 = (C1, C2, C3, C4)          Ci = (kp*ui)/tau2^2
//   c1 = (A, mn, mx, kTh)          A  = (-2*damp)*tau2
//   c2 = (kTo, Cd, IBxx, IByy)
//   c3 = (IBzz, dxm, dym, label)
__device__ float4 g_pack[(size_t)NSTEP * B_DIM * 4]; // ~134 MB
__device__ double g_part[PREP_BLOCKS];               // block partial sums of kTh
__device__ float  g_hover;
__device__ double g_loss[B_DIM];

// scale(k, base) with exact reference association: ((0.5-g)*95.0)/100.0
__device__ __forceinline__ float sc(float g, float base) {
    float t = (0.5f - g) * 95.0f;
    t = t / 100.0f;
    return (1.0f + t) * base;
}

// ---------------------------------------------------------------------------
// Kernel 1: precompute packed coefficients + partial sums of kTh (for hover)
// grid = 8192 x 256, one thread per (t,b)
// ---------------------------------------------------------------------------
__global__ void __launch_bounds__(256) prep_kernel(
    const float* __restrict__ logits,
    const float* __restrict__ u1p, const float* __restrict__ u2p,
    const float* __restrict__ u3p, const float* __restrict__ u4p,
    const float* __restrict__ maxp, const float* __restrict__ minp,
    const float* __restrict__ lab)
{
    const int idx = blockIdx.x * 256 + threadIdx.x; // < NELEM
    const float4* lg = reinterpret_cast<const float4*>(logits) + (size_t)idx * 3;
    float4 l0 = lg[0]; // ch 0..3
    float4 l1 = lg[1]; // ch 4..7
    float4 l2 = lg[2]; // ch 8..11

    float kTh = sc(l1.w, 1.076e-05f);

    // deterministic block reduction of kTh (double)
    __shared__ double red[256];
    red[threadIdx.x] = (double)kTh;
    __syncthreads();
    #pragma unroll
    for (int s = 128; s > 0; s >>= 1) {
        if (threadIdx.x < s) red[threadIdx.x] += red[threadIdx.x + s];
        __syncthreads();
    }
    if (threadIdx.x == 0) g_part[blockIdx.x] = red[0];

    const int t = idx >> 9;
    const int b = idx & 511;
    if (t >= 1) {
        float dxm  = sc(l0.x, 0.16f);
        float dym  = sc(l0.y, 0.16f);
        float IBxx = sc(l0.w, 0.0123f);
        float IByy = sc(l1.x, 0.0123f);
        float IBzz = sc(l1.y, 0.0123f);
        float Cd   = sc(l1.z, 0.1f);
        float kTo  = sc(l2.x, 1.632e-07f);
        float tau2 = sc(l2.y, 0.015f);
        float kp   = sc(l2.z, 1.0f);
        float damp = sc(l2.w, 1.0f);

        float A   = (-2.0f * damp) * tau2;      // ((-2*damp)*tau2)
        float t2s = tau2 * tau2;                // tau2**2
        float C1 = (kp * u1p[idx]) / t2s;
        float C2 = (kp * u2p[idx]) / t2s;
        float C3 = (kp * u3p[idx]) / t2s;
        float C4 = (kp * u4p[idx]) / t2s;

        size_t o = ((size_t)(t - 1) * B_DIM + b) * 4;
        g_pack[o + 0] = make_float4(C1, C2, C3, C4);
        g_pack[o + 1] = make_float4(A, minp[idx], maxp[idx], kTh);
        g_pack[o + 2] = make_float4(kTo, Cd, IBxx, IByy);
        g_pack[o + 3] = make_float4(IBzz, dxm, dym, lab[idx]);
    }
}

// ---------------------------------------------------------------------------
// Kernel 2: finalize hover = sqrt(max(mB*g/(4*mean(kTh)+eps), 1e-6))
// ---------------------------------------------------------------------------
__global__ void hover_kernel()
{
    __shared__ double red[256];
    double s = 0.0;
    for (int i = threadIdx.x; i < PREP_BLOCKS; i += 256) s += g_part[i];
    red[threadIdx.x] = s;
    __syncthreads();
    #pragma unroll
    for (int st = 128; st > 0; st >>= 1) {
        if (threadIdx.x < st) red[threadIdx.x] += red[threadIdx.x + st];
        __syncthreads();
    }
    if (threadIdx.x == 0) {
        float m   = (float)(red[0] / (double)NELEM);
        float den = 4.0f * m + 1e-12f;
        float v   = (float)(1.2 * 9.81) / den;
        v = fmaxf(v, 1e-6f);
        g_hover = sqrtf(v);
    }
}

// ---------------------------------------------------------------------------
// Kernel 3: serial simulation. 16 blocks x 32 threads, 1 thread per trajectory.
// 4-slot register ring prefetches packed inputs 3+ iterations ahead.
// ---------------------------------------------------------------------------
__global__ void __launch_bounds__(32, 1) sim_kernel(const float* __restrict__ labels)
{
    const int b = blockIdx.x * 32 + threadIdx.x;
    const float tau  = 0.005f;
    const float mB   = 1.2f;
    const float gmB  = (float)(9.81 * 1.2);
    const float UPIR = 1e-4f; // uP * IRzz

    const float hover = g_hover;

    // live state (x/y position & velocity are dead w.r.t. the loss -> dropped)
    float xz = 0.f;
    float q0 = 1.f, q1 = 0.f, q2 = 0.f, q3 = 0.f;
    float zd = 0.f, pv = 0.f, qv = 0.f, rv = 0.f;
    float w1 = hover, w2 = hover, w3 = hover, w4 = hover;
    float wd1 = 0.f, wd2 = 0.f, wd3 = 0.f, wd4 = 0.f;

    double acc;
    { float l0 = labels[b]; acc = (double)l0 * (double)l0; } // (0 - actual_z[0])^2

    const float4* __restrict__ base = g_pack + (size_t)b * 4; // step i at base + i*2048

    float4 buf[4][4];
    #pragma unroll
    for (int j = 0; j < 3; ++j) {
        const float4* p = base + (size_t)j * (B_DIM * 4);
        buf[j][0] = p[0]; buf[j][1] = p[1]; buf[j][2] = p[2]; buf[j][3] = p[3];
    }

    auto step = [&](const float4 c0, const float4 c1, const float4 c2, const float4 c3) {
        const float C1 = c0.x, C2 = c0.y, C3 = c0.z, C4 = c0.w;
        const float A  = c1.x, mn = c1.y, mx = c1.z, kTh = c1.w;
        const float kTo = c2.x, Cd = c2.y, IBxx = c2.z, IByy = c2.w;
        const float IBzz = c3.x, dxm = c3.y, dym = c3.z, lbl = c3.w;

        // motor accelerations (A, Ci hoisted; association matches reference)
        float wdd1 = (A * wd1 - w1) + C1;
        float wdd2 = (A * wd2 - w2) + C2;
        float wdd3 = (A * wd3 - w3) + C3;
        float wdd4 = (A * wd4 - w4) + C4;

        float w1c = fminf(fmaxf(w1, mn), mx);
        float w2c = fminf(fmaxf(w2, mn), mx);
        float w3c = fminf(fmaxf(w3, mn), mx);
        float w4c = fminf(fmaxf(w4, mn), mx);

        float s1 = w1c * w1c, s2 = w2c * w2c, s3 = w3c * w3c, s4 = w4c * w4c;
        float T1 = kTh * s1, T2 = kTh * s2, T3 = kTh * s3, T4 = kTh * s4;
        float Q1 = kTo * s1, Q2 = kTo * s2, Q3 = kTo * s3, Q4 = kTo * s4;
        float Thr = ((T1 + T2) + T3) + T4;

        // z velocity
        float sz = (zd > 0.f) ? 1.f : ((zd < 0.f) ? -1.f : 0.f);
        float qq = ((q0 * q0 - q1 * q1) - q2 * q2) + q3 * q3;
        float innz = ((((-Cd) * sz) * (zd * zd)) + Thr * qq) - gmB;
        float nzd = zd + (tau * innz) / mB;

        // quaternion
        float hp = 0.5f * pv, hq = 0.5f * qv, hr = 0.5f * rv;
        float nq0 = q0 + tau * ((((-hp) * q1) - hq * q2) - hr * q3);
        float nq1 = q1 + tau * (((hp * q0) - hq * q3) + hr * q2);
        float nq2 = q2 + tau * (((hp * q3) + hq * q0) - hr * q1);
        float nq3 = q3 + tau * ((((-hp) * q2) + hq * q1) + hr * q0);

        // body rates
        float wsum = ((w1c - w2c) + w3c) - w4c;
        float tpm = ((T1 - T2) - T3) + T4;
        float tpp = ((T1 + T2) - T3) - T4;
        float npv = pv + (tau * ((((IByy - IBzz) * qv) * rv - ((UPIR * wsum) * qv)) + (tpm * dym))) / IBxx;
        float nqv = qv + (tau * (((((IBzz - IBxx) * pv) * rv) + ((UPIR * wsum) * pv)) + (tpp * dxm))) / IByy;
        float nrv = rv + (tau * ((((((IBxx - IByy) * pv) * qv - Q1) + Q2) - Q3) + Q4)) / IBzz;

        float nxz_raw = xz + tau * nzd;

        float nw1 = w1c + tau * wd1;
        float nw2 = w2c + tau * wd2;
        float nw3 = w3c + tau * wd3;
        float nw4 = w4c + tau * wd4;
        float nwd1 = wd1 + tau * wdd1;
        float nwd2 = wd2 + tau * wdd2;
        float nwd3 = wd3 + tau * wdd3;
        float nwd4 = wd4 + tau * wdd4;

        bool ok = isfinite(nxz_raw) && (fabsf(nxz_raw - xz) <= 400.0f);
        float nxz = ok ? nxz_raw : xz;

        float dz = nxz - lbl;
        acc = fma((double)dz, (double)dz, acc);

        // commit
        xz = nxz;
        q0 = nq0; q1 = nq1; q2 = nq2; q3 = nq3;
        zd = nzd; pv = npv; qv = nqv; rv = nrv;
        w1 = nw1; w2 = nw2; w3 = nw3; w4 = nw4;
        wd1 = nwd1; wd2 = nwd2; wd3 = nwd3; wd4 = nwd4;
    };

    #define LOADS(ii, slot) { \
        const float4* p = base + (size_t)(ii) * (B_DIM * 4); \
        buf[slot][0] = p[0]; buf[slot][1] = p[1]; \
        buf[slot][2] = p[2]; buf[slot][3] = p[3]; }
    #define STEP(slot) step(buf[slot][0], buf[slot][1], buf[slot][2], buf[slot][3]);

    // main loop: 4092 iters (multiple of 4); loads stay >= 3 iterations ahead
    for (int i = 0; i < 4092; i += 4) {
        LOADS(i + 3, 3) STEP(0)
        LOADS(i + 4, 0) STEP(1)
        LOADS(i + 5, 1) STEP(2)
        LOADS(i + 6, 2) STEP(3)
    }
    // epilogue: i = 4092, 4093, 4094 (slots 0,1,2 already loaded)
    STEP(0)
    STEP(1)
    STEP(2)

    #undef LOADS
    #undef STEP

    g_loss[b] = acc;
}

// ---------------------------------------------------------------------------
// Kernel 4: deterministic loss reduction -> mean
// ---------------------------------------------------------------------------
__global__ void loss_kernel(float* __restrict__ out)
{
    __shared__ double red[B_DIM];
    red[threadIdx.x] = g_loss[threadIdx.x];
    __syncthreads();
    #pragma unroll
    for (int s = 256; s > 0; s >>= 1) {
        if (threadIdx.x < s) red[threadIdx.x] += red[threadIdx.x + s];
        __syncthreads();
    }
    if (threadIdx.x == 0) out[0] = (float)(red[0] / (double)NELEM);
}

// ---------------------------------------------------------------------------
// Launch
// ---------------------------------------------------------------------------
extern "C" void kernel_launch(void* const* d_in, const int* in_sizes, int n_in,
                              void* d_out, int out_size)
{
    const float* labels = (const float*)d_in[0];
    const float* logits = (const float*)d_in[1];
    const float* u1     = (const float*)d_in[2];
    const float* u2     = (const float*)d_in[3];
    const float* u3     = (const float*)d_in[4];
    const float* u4     = (const float*)d_in[5];
    const float* maxM   = (const float*)d_in[6];
    const float* minM   = (const float*)d_in[7];

    prep_kernel<<<PREP_BLOCKS, 256>>>(logits, u1, u2, u3, u4, maxM, minM, labels);
    hover_kernel<<<1, 256>>>();
    sim_kernel<<<16, 32>>>(labels);
    loss_kernel<<<1, B_DIM>>>((float*)d_out);
}

// round 3
// speedup vs baseline: 1.7785x; 1.7785x over previous
#include <cuda_runtime.h>
#include <math.h>
#include <stdint.h>

// Problem dims
#define T_DIM 4096
#define B_DIM 512
#define NSTEP 4095                 // scan steps (t = 1..4095)
#define NSTEP_PAD 4104             // padded so the 6-deep prefetch ring needs no guards
#define NELEM (T_DIM * B_DIM)      // 2,097,152
#define PREP_BLOCKS (NELEM / 256)  // 8192

// ---------------------------------------------------------------------------
// Device scratch (static: no allocations allowed)
// Packed per-(step, b) folded coefficients: 5 x float4 per element (80 B).
//   p0 = (C1, C2, C3, C4)            Ci   = (kp*ui)/tau2^2
//   p1 = (A,  mn, mx, label)         A    = (-2*damp)*tau2
//   p2 = (Cd', kThz, kThd1, kThd2)   Cd'  = Cd*tau/mB, kThz = kTh*tau/mB
//                                    kThd1= kTh*dym*tau/IBxx, kThd2 = kTh*dxm*tau/IByy
//   p3 = (e1, u1, e2, u2)            e1=(IByy-IBzz)*tau/IBxx, u1=uP*IRzz*tau/IBxx
//                                    e2=(IBzz-IBxx)*tau/IByy, u2=uP*IRzz*tau/IByy
//   p4 = (e3, kTo', 0, 0)            e3=(IBxx-IByy)*tau/IBzz, kTo'=kTo*tau/IBzz
// ---------------------------------------------------------------------------
__device__ float4 g_pack[(size_t)NSTEP_PAD * B_DIM * 5]; // ~168 MB
__device__ double g_part[PREP_BLOCKS];
__device__ float  g_hover;
__device__ double g_loss[B_DIM];

__device__ __forceinline__ float sc(float g, float base) {
    float t = (0.5f - g) * 95.0f;
    t = t / 100.0f;
    return (1.0f + t) * base;
}

// ---------------------------------------------------------------------------
// Kernel 1: precompute folded coefficients + partial sums of kTh (for hover)
// ---------------------------------------------------------------------------
__global__ void __launch_bounds__(256) prep_kernel(
    const float* __restrict__ logits,
    const float* __restrict__ u1p, const float* __restrict__ u2p,
    const float* __restrict__ u3p, const float* __restrict__ u4p,
    const float* __restrict__ maxp, const float* __restrict__ minp,
    const float* __restrict__ lab)
{
    const int idx = blockIdx.x * 256 + threadIdx.x;
    const float4* lg = reinterpret_cast<const float4*>(logits) + (size_t)idx * 3;
    float4 l0 = lg[0]; // ch 0..3
    float4 l1 = lg[1]; // ch 4..7
    float4 l2 = lg[2]; // ch 8..11

    float kTh = sc(l1.w, 1.076e-05f);

    __shared__ double red[256];
    red[threadIdx.x] = (double)kTh;
    __syncthreads();
    #pragma unroll
    for (int s = 128; s > 0; s >>= 1) {
        if (threadIdx.x < s) red[threadIdx.x] += red[threadIdx.x + s];
        __syncthreads();
    }
    if (threadIdx.x == 0) g_part[blockIdx.x] = red[0];

    const int t = idx >> 9;
    const int b = idx & 511;
    if (t >= 1) {
        const float tau = 0.005f;
        const float TM  = (float)(0.005 / 1.2);       // tau / mB
        const float UPT = (float)(1e-4 * 0.005);      // uP*IRzz*tau

        float dxm  = sc(l0.x, 0.16f);
        float dym  = sc(l0.y, 0.16f);
        float IBxx = sc(l0.w, 0.0123f);
        float IByy = sc(l1.x, 0.0123f);
        float IBzz = sc(l1.y, 0.0123f);
        float Cd   = sc(l1.z, 0.1f);
        float kTo  = sc(l2.x, 1.632e-07f);
        float tau2 = sc(l2.y, 0.015f);
        float kp   = sc(l2.z, 1.0f);
        float damp = sc(l2.w, 1.0f);

        float A   = (-2.0f * damp) * tau2;
        float t2s = tau2 * tau2;
        float C1 = (kp * u1p[idx]) / t2s;
        float C2 = (kp * u2p[idx]) / t2s;
        float C3 = (kp * u3p[idx]) / t2s;
        float C4 = (kp * u4p[idx]) / t2s;

        float Cdz   = Cd * TM;
        float kThz  = kTh * TM;
        float kThd1 = ((kTh * dym) * tau) / IBxx;
        float kThd2 = ((kTh * dxm) * tau) / IByy;
        float e1 = ((IByy - IBzz) * tau) / IBxx;
        float u1 = UPT / IBxx;
        float e2 = ((IBzz - IBxx) * tau) / IByy;
        float u2 = UPT / IByy;
        float e3 = ((IBxx - IByy) * tau) / IBzz;
        float kToz = (kTo * tau) / IBzz;

        size_t o = ((size_t)(t - 1) * B_DIM + b) * 5;
        g_pack[o + 0] = make_float4(C1, C2, C3, C4);
        g_pack[o + 1] = make_float4(A, minp[idx], maxp[idx], lab[idx]);
        g_pack[o + 2] = make_float4(Cdz, kThz, kThd1, kThd2);
        g_pack[o + 3] = make_float4(e1, u1, e2, u2);
        g_pack[o + 4] = make_float4(e3, kToz, 0.f, 0.f);
    }
}

// ---------------------------------------------------------------------------
// Kernel 2: hover = sqrt(max(mB*g/(4*mean(kTh)+eps), 1e-6))
// ---------------------------------------------------------------------------
__global__ void hover_kernel()
{
    __shared__ double red[256];
    double s = 0.0;
    for (int i = threadIdx.x; i < PREP_BLOCKS; i += 256) s += g_part[i];
    red[threadIdx.x] = s;
    __syncthreads();
    #pragma unroll
    for (int st = 128; st > 0; st >>= 1) {
        if (threadIdx.x < st) red[threadIdx.x] += red[threadIdx.x + st];
        __syncthreads();
    }
    if (threadIdx.x == 0) {
        float m   = (float)(red[0] / (double)NELEM);
        float den = 4.0f * m + 1e-12f;
        float v   = (float)(1.2 * 9.81) / den;
        v = fmaxf(v, 1e-6f);
        g_hover = sqrtf(v);
    }
}

// ---------------------------------------------------------------------------
// Kernel 3: serial simulation. 16 blocks x 32 threads, 1 thread/trajectory.
// Division-free inner loop; 6-deep register prefetch ring.
// ---------------------------------------------------------------------------
__global__ void __launch_bounds__(32, 1) sim_kernel(const float* __restrict__ labels)
{
    const int b = blockIdx.x * 32 + threadIdx.x;
    const float tau = 0.005f;
    const float HT  = 0.0025f;   // tau * 0.5
    const float GT  = 0.04905f;  // g * tau

    const float hover = g_hover;

    float xz = 0.f;
    float q0 = 1.f, q1 = 0.f, q2 = 0.f, q3 = 0.f;
    float zd = 0.f, pv = 0.f, qv = 0.f, rv = 0.f;
    float w1 = hover, w2 = hover, w3 = hover, w4 = hover;
    float wd1 = 0.f, wd2 = 0.f, wd3 = 0.f, wd4 = 0.f;

    double acc;
    { float l0 = labels[b]; acc = (double)l0 * (double)l0; }

    const float4* __restrict__ base = g_pack + (size_t)b * 5;
    const size_t STRIDE = (size_t)B_DIM * 5; // float4s per step

    float4 buf[6][5];
    #pragma unroll
    for (int j = 0; j < 6; ++j) {
        const float4* p = base + (size_t)j * STRIDE;
        buf[j][0] = p[0]; buf[j][1] = p[1]; buf[j][2] = p[2];
        buf[j][3] = p[3]; buf[j][4] = p[4];
    }

    float accf = 0.f;

    auto step = [&](const float4 p0, const float4 p1, const float4 p2,
                    const float4 p3, const float4 p4) {
        // motor accelerations
        float wdd1 = fmaf(p1.x, wd1, -w1) + p0.x;
        float wdd2 = fmaf(p1.x, wd2, -w2) + p0.y;
        float wdd3 = fmaf(p1.x, wd3, -w3) + p0.z;
        float wdd4 = fmaf(p1.x, wd4, -w4) + p0.w;

        float w1c = fminf(fmaxf(w1, p1.y), p1.z);
        float w2c = fminf(fmaxf(w2, p1.y), p1.z);
        float w3c = fminf(fmaxf(w3, p1.y), p1.z);
        float w4c = fminf(fmaxf(w4, p1.y), p1.z);

        float s1 = w1c * w1c, s2 = w2c * w2c, s3 = w3c * w3c, s4 = w4c * w4c;
        float a12 = s1 + s2, a34 = s3 + s4;
        float d12 = s1 - s2, d34 = s3 - s4;
        float sa = a12 + a34;          // s1+s2+s3+s4
        float sp = a12 - a34;          // s1+s2-s3-s4
        float sm = d12 - d34;          // s1-s2-s3+s4
        float sq = -(d12 + d34);       // -s1+s2-s3+s4

        float Thr = p2.y * sa;         // kTh*tau/mB * Σs

        // z velocity (tau/mB folded)
        float zd2 = zd * zd;
        float qq  = ((q0 * q0 - q1 * q1) - q2 * q2) + q3 * q3;
        float sz  = (zd > 0.f) ? 1.f : ((zd < 0.f) ? -1.f : 0.f);
        float drag = p2.x * (sz * zd2);
        float nzd = zd + ((Thr * qq - drag) - GT);

        // quaternion (tau*0.5 folded)
        float hp = HT * pv, hq = HT * qv, hr = HT * rv;
        float t0 = hp * q1; t0 = fmaf(hq, q2, t0); t0 = fmaf(hr, q3, t0);
        float nq0 = q0 - t0;
        float t1 = hp * q0; t1 = fmaf(-hq, q3, t1); t1 = fmaf(hr, q2, t1);
        float nq1 = q1 + t1;
        float t2 = hp * q3; t2 = fmaf(hq, q0, t2); t2 = fmaf(-hr, q1, t2);
        float nq2 = q2 + t2;
        float t3 = -hp * q2; t3 = fmaf(hq, q1, t3); t3 = fmaf(hr, q0, t3);
        float nq3 = q3 + t3;

        // body rates (all divisions pre-folded)
        float qvrv = qv * rv, pvrv = pv * rv, pvqv = pv * qv;
        float wsum = ((w1c - w2c) + w3c) - w4c;
        float wq = wsum * qv, wp = wsum * pv;
        float r1 = p3.x * qvrv; r1 = fmaf(-p3.y, wq, r1); r1 = fmaf(p2.z, sm, r1);
        float npv = pv + r1;
        float r2 = p3.z * pvrv; r2 = fmaf(p3.w, wp, r2); r2 = fmaf(p2.w, sp, r2);
        float nqv = qv + r2;
        float r3 = p4.x * pvqv; r3 = fmaf(p4.y, sq, r3);
        float nrv = rv + r3;

        float nxz_raw = fmaf(tau, nzd, xz);

        float nw1 = fmaf(tau, wd1, w1c);
        float nw2 = fmaf(tau, wd2, w2c);
        float nw3 = fmaf(tau, wd3, w3c);
        float nw4 = fmaf(tau, wd4, w4c);
        float nwd1 = fmaf(tau, wdd1, wd1);
        float nwd2 = fmaf(tau, wdd2, wd2);
        float nwd3 = fmaf(tau, wdd3, wd3);
        float nwd4 = fmaf(tau, wdd4, wd4);

        // mask: |diff|<=400 is false for NaN/Inf diff, and xz is always finite,
        // so this is equivalent to isfinite(nxz_raw) && |diff|<=400
        float diff = nxz_raw - xz;
        float nxz = (fabsf(diff) <= 400.0f) ? nxz_raw : xz;

        float dz = nxz - p1.w;
        accf = fmaf(dz, dz, accf);

        xz = nxz;
        q0 = nq0; q1 = nq1; q2 = nq2; q3 = nq3;
        zd = nzd; pv = npv; qv = nqv; rv = nrv;
        w1 = nw1; w2 = nw2; w3 = nw3; w4 = nw4;
        wd1 = nwd1; wd2 = nwd2; wd3 = nwd3; wd4 = nwd4;
    };

    #define LOADS(ii, slot) { \
        const float4* p = base + (size_t)(ii) * STRIDE; \
        buf[slot][0] = p[0]; buf[slot][1] = p[1]; buf[slot][2] = p[2]; \
        buf[slot][3] = p[3]; buf[slot][4] = p[4]; }
    #define STEP(slot) step(buf[slot][0], buf[slot][1], buf[slot][2], \
                            buf[slot][3], buf[slot][4]);

    // 682 bodies x 6 steps = steps 0..4091; loads run 6 steps ahead (padded pack)
    for (int i = 0; i < 4092; i += 6) {
        STEP(0) LOADS(i + 6,  0)
        STEP(1) LOADS(i + 7,  1)
        STEP(2) LOADS(i + 8,  2)
        STEP(3) LOADS(i + 9,  3)
        STEP(4) LOADS(i + 10, 4)
        STEP(5) LOADS(i + 11, 5)
        acc += (double)accf;
        accf = 0.f;
    }
    // epilogue: steps 4092..4094 live in slots 0..2
    STEP(0)
    STEP(1)
    STEP(2)
    acc += (double)accf;

    #undef LOADS
    #undef STEP

    g_loss[b] = acc;
}

// ---------------------------------------------------------------------------
// Kernel 4: deterministic loss reduction -> mean
// ---------------------------------------------------------------------------
__global__ void loss_kernel(float* __restrict__ out)
{
    __shared__ double red[B_DIM];
    red[threadIdx.x] = g_loss[threadIdx.x];
    __syncthreads();
    #pragma unroll
    for (int s = 256; s > 0; s >>= 1) {
        if (threadIdx.x < s) red[threadIdx.x] += red[threadIdx.x + s];
        __syncthreads();
    }
    if (threadIdx.x == 0) out[0] = (float)(red[0] / (double)NELEM);
}

// ---------------------------------------------------------------------------
// Launch
// ---------------------------------------------------------------------------
extern "C" void kernel_launch(void* const* d_in, const int* in_sizes, int n_in,
                              void* d_out, int out_size)
{
    const float* labels = (const float*)d_in[0];
    const float* logits = (const float*)d_in[1];
    const float* u1     = (const float*)d_in[2];
    const float* u2     = (const float*)d_in[3];
    const float* u3     = (const float*)d_in[4];
    const float* u4     = (const float*)d_in[5];
    const float* maxM   = (const float*)d_in[6];
    const float* minM   = (const float*)d_in[7];

    prep_kernel<<<PREP_BLOCKS, 256>>>(logits, u1, u2, u3, u4, maxM, minM, labels);
    hover_kernel<<<1, 256>>>();
    sim_kernel<<<16, 32>>>(labels);
    loss_kernel<<<1, B_DIM>>>((float*)d_out);
}

// round 4
// speedup vs baseline: 1.8791x; 1.0565x over previous
#include <cuda_runtime.h>
#include <math.h>
#include <stdint.h>

// Problem dims
#define T_DIM 4096
#define B_DIM 512
#define NSTEP 4095
#define NSTEP_PAD 4104             // padded: 6-deep prefetch ring needs no guards
#define NELEM (T_DIM * B_DIM)      // 2,097,152
#define PREP_BLOCKS (NELEM / 256)  // 8192

// ---------------------------------------------------------------------------
// Packed per-(step,b) folded coefficients: 5 x float4 (80 B), lanes arranged
// for f32x2 consumption:
//   p0 = (C1, C3, C2, C4)            pairs (C1,C3) motors{1,3}, (C2,C4) {2,4}
//   p1 = (A,  mn, mx, label)
//   p2 = (Cd', kThz, kThd1, kThd2)   pair (kThd1,kThd2)
//   p3 = (e1, e2, -u1, u2)           pairs (e1,e2), (-u1,u2)
//   p4 = (e3, -kTo', 0, 0)
// ---------------------------------------------------------------------------
__device__ float4 g_pack[(size_t)NSTEP_PAD * B_DIM * 5]; // ~168 MB
__device__ double g_part[PREP_BLOCKS];
__device__ float  g_hover;
__device__ double g_loss[B_DIM];

// ---------------------------------------------------------------------------
// f32x2 packed helpers (sm_100a)
// ---------------------------------------------------------------------------
union F2U { float2 f; unsigned long long u; };

__device__ __forceinline__ float2 mul2(float2 a, float2 b) {
    F2U A, B, R; A.f = a; B.f = b;
    asm("mul.rn.f32x2 %0, %1, %2;" : "=l"(R.u) : "l"(A.u), "l"(B.u));
    return R.f;
}
__device__ __forceinline__ float2 add2(float2 a, float2 b) {
    F2U A, B, R; A.f = a; B.f = b;
    asm("add.rn.f32x2 %0, %1, %2;" : "=l"(R.u) : "l"(A.u), "l"(B.u));
    return R.f;
}
__device__ __forceinline__ float2 fma2(float2 a, float2 b, float2 c) {
    F2U A, B, C, R; A.f = a; B.f = b; C.f = c;
    asm("fma.rn.f32x2 %0, %1, %2, %3;" : "=l"(R.u) : "l"(A.u), "l"(B.u), "l"(C.u));
    return R.f;
}
// exact packed subtraction: a - b == fma(b, -1, a)
__device__ __forceinline__ float2 sub2(float2 a, float2 b) {
    return fma2(b, make_float2(-1.0f, -1.0f), a);
}

__device__ __forceinline__ float sc(float g, float base) {
    float t = (0.5f - g) * 95.0f;
    t = t / 100.0f;
    return (1.0f + t) * base;
}

// ---------------------------------------------------------------------------
// Kernel 1: precompute folded coefficients + partial sums of kTh (for hover)
// ---------------------------------------------------------------------------
__global__ void __launch_bounds__(256) prep_kernel(
    const float* __restrict__ logits,
    const float* __restrict__ u1p, const float* __restrict__ u2p,
    const float* __restrict__ u3p, const float* __restrict__ u4p,
    const float* __restrict__ maxp, const float* __restrict__ minp,
    const float* __restrict__ lab)
{
    const int idx = blockIdx.x * 256 + threadIdx.x;
    const float4* lg = reinterpret_cast<const float4*>(logits) + (size_t)idx * 3;
    float4 l0 = lg[0];
    float4 l1 = lg[1];
    float4 l2 = lg[2];

    float kTh = sc(l1.w, 1.076e-05f);

    __shared__ double red[256];
    red[threadIdx.x] = (double)kTh;
    __syncthreads();
    #pragma unroll
    for (int s = 128; s > 0; s >>= 1) {
        if (threadIdx.x < s) red[threadIdx.x] += red[threadIdx.x + s];
        __syncthreads();
    }
    if (threadIdx.x == 0) g_part[blockIdx.x] = red[0];

    const int t = idx >> 9;
    const int b = idx & 511;
    if (t >= 1) {
        const float tau = 0.005f;
        const float TM  = (float)(0.005 / 1.2);   // tau / mB
        const float UPT = (float)(1e-4 * 0.005);  // uP*IRzz*tau

        float dxm  = sc(l0.x, 0.16f);
        float dym  = sc(l0.y, 0.16f);
        float IBxx = sc(l0.w, 0.0123f);
        float IByy = sc(l1.x, 0.0123f);
        float IBzz = sc(l1.y, 0.0123f);
        float Cd   = sc(l1.z, 0.1f);
        float kTo  = sc(l2.x, 1.632e-07f);
        float tau2 = sc(l2.y, 0.015f);
        float kp   = sc(l2.z, 1.0f);
        float damp = sc(l2.w, 1.0f);

        float A   = (-2.0f * damp) * tau2;
        float t2s = tau2 * tau2;
        float C1 = (kp * u1p[idx]) / t2s;
        float C2 = (kp * u2p[idx]) / t2s;
        float C3 = (kp * u3p[idx]) / t2s;
        float C4 = (kp * u4p[idx]) / t2s;

        float Cdz   = Cd * TM;
        float kThz  = kTh * TM;
        float kThd1 = ((kTh * dym) * tau) / IBxx;
        float kThd2 = ((kTh * dxm) * tau) / IByy;
        float e1 = ((IByy - IBzz) * tau) / IBxx;
        float u1 = UPT / IBxx;
        float e2 = ((IBzz - IBxx) * tau) / IByy;
        float u2 = UPT / IByy;
        float e3 = ((IBxx - IByy) * tau) / IBzz;
        float kToz = (kTo * tau) / IBzz;

        size_t o = ((size_t)(t - 1) * B_DIM + b) * 5;
        g_pack[o + 0] = make_float4(C1, C3, C2, C4);
        g_pack[o + 1] = make_float4(A, minp[idx], maxp[idx], lab[idx]);
        g_pack[o + 2] = make_float4(Cdz, kThz, kThd1, kThd2);
        g_pack[o + 3] = make_float4(e1, e2, -u1, u2);
        g_pack[o + 4] = make_float4(e3, -kToz, 0.f, 0.f);
    }
}

// ---------------------------------------------------------------------------
// Kernel 2: hover = sqrt(max(mB*g/(4*mean(kTh)+eps), 1e-6))
// ---------------------------------------------------------------------------
__global__ void hover_kernel()
{
    __shared__ double red[256];
    double s = 0.0;
    for (int i = threadIdx.x; i < PREP_BLOCKS; i += 256) s += g_part[i];
    red[threadIdx.x] = s;
    __syncthreads();
    #pragma unroll
    for (int st = 128; st > 0; st >>= 1) {
        if (threadIdx.x < st) red[threadIdx.x] += red[threadIdx.x + st];
        __syncthreads();
    }
    if (threadIdx.x == 0) {
        float m   = (float)(red[0] / (double)NELEM);
        float den = 4.0f * m + 1e-12f;
        float v   = (float)(1.2 * 9.81) / den;
        v = fmaxf(v, 1e-6f);
        g_hover = sqrtf(v);
    }
}

// ---------------------------------------------------------------------------
// Kernel 3: serial simulation. 16 blocks x 32 threads, 1 thread/trajectory.
// f32x2-packed, division-free inner loop; 6-deep register prefetch ring.
// ---------------------------------------------------------------------------
__global__ void __launch_bounds__(32, 1) sim_kernel(const float* __restrict__ labels)
{
    const int b = blockIdx.x * 32 + threadIdx.x;
    const float tau = 0.005f;
    const float HT  = 0.0025f;   // tau * 0.5
    const float GT  = 0.04905f;  // g * tau

    // loop-invariant packed constants
    const float2 TAUD = make_float2(tau,  tau);
    const float2 HTmp = make_float2(-HT,  HT);
    const float2 HTpm = make_float2( HT, -HT);
    const float2 HTn2 = make_float2(-HT, -HT);
    const float2 HTp2 = make_float2( HT,  HT);

    const float hover = g_hover;

    float xz = 0.f;
    float q0 = 1.f, q1 = 0.f, q2 = 0.f, q3 = 0.f;
    float zd = 0.f, pv = 0.f, qv = 0.f, rv = 0.f;
    // packed motor state: pairs (1,3) and (2,4)
    float2 Wa = make_float2(hover, hover);
    float2 Wb = make_float2(hover, hover);
    float2 Da = make_float2(0.f, 0.f);
    float2 Db = make_float2(0.f, 0.f);

    double acc;
    { float l0 = labels[b]; acc = (double)l0 * (double)l0; }

    const float4* __restrict__ base = g_pack + (size_t)b * 5;
    const size_t STRIDE = (size_t)B_DIM * 5;

    float4 buf[6][5];
    #pragma unroll
    for (int j = 0; j < 6; ++j) {
        const float4* p = base + (size_t)j * STRIDE;
        buf[j][0] = p[0]; buf[j][1] = p[1]; buf[j][2] = p[2];
        buf[j][3] = p[3]; buf[j][4] = p[4];
    }

    float accf = 0.f;

    auto step = [&](const float4 p0, const float4 p1, const float4 p2,
                    const float4 p3, const float4 p4) {
        const float2 C13 = make_float2(p0.x, p0.y);
        const float2 C24 = make_float2(p0.z, p0.w);
        const float2 A2  = make_float2(p1.x, p1.x);
        const float mn = p1.y, mx = p1.z, lbl = p1.w;
        const float Cdz = p2.x, kThz = p2.y;
        const float2 K  = make_float2(p2.z, p2.w);   // (kThd1, kThd2)
        const float2 E  = make_float2(p3.x, p3.y);   // (e1, e2)
        const float2 U  = make_float2(p3.z, p3.w);   // (-u1, u2)
        const float e3 = p4.x, nkToz = p4.y;

        // motor accelerations: (A*wd + C) - w
        float2 wddA = sub2(fma2(A2, Da, C13), Wa);
        float2 wddB = sub2(fma2(A2, Db, C24), Wb);

        // clip (scalar FMNMX, alu pipe)
        float2 WaC = make_float2(fminf(fmaxf(Wa.x, mn), mx),
                                 fminf(fmaxf(Wa.y, mn), mx));
        float2 WbC = make_float2(fminf(fmaxf(Wb.x, mn), mx),
                                 fminf(fmaxf(Wb.y, mn), mx));

        float2 Sa = mul2(WaC, WaC);   // (s1, s3)
        float2 Sb = mul2(WbC, WbC);   // (s2, s4)
        float2 aP = add2(Sa, Sb);     // (a12, a34)
        float2 dP = sub2(Sa, Sb);     // (d12, d34)
        float sa  = aP.x + aP.y;      // s1+s2+s3+s4
        float spp = aP.x - aP.y;      // s1+s2-s3-s4
        float smm = dP.x - dP.y;      // s1-s2-s3+s4
        float sqn = dP.x + dP.y;      // = -sq
        float2 dW = sub2(WaC, WbC);   // (w1c-w2c, w3c-w4c)
        float wsum = dW.x + dW.y;

        float Thr = kThz * sa;

        // quaternion magnitude term qq (packed squares)
        float2 Qa  = make_float2(q1, q3);
        float2 Qb  = make_float2(q2, q0);
        float2 Qas = make_float2(q3, q1);
        float2 Qbs = make_float2(q0, q2);
        float2 Z1 = mul2(Qbs, Qbs);   // (q0^2, q2^2)
        float2 Z2 = mul2(Qa,  Qa);    // (q1^2, q3^2)
        float2 Zd = sub2(Z1, Z2);     // (q0^2-q1^2, q2^2-q3^2)
        float qq = Zd.x - Zd.y;

        // z velocity
        float zd2 = zd * zd;
        float sz  = (zd > 0.f) ? 1.f : ((zd < 0.f) ? -1.f : 0.f);
        float drag = Cdz * (sz * zd2);
        float nzd = zd + ((Thr * qq - drag) - GT);

        // quaternion update via sign-mixed packed halves
        float2 pvd = make_float2(pv, pv);
        float2 qvd = make_float2(qv, qv);
        float2 rvd = make_float2(rv, rv);
        float2 hpmn = mul2(HTmp, pvd);   // (-hp,  hp)
        float2 hpm  = mul2(HTpm, pvd);   // ( hp, -hp)
        float2 hqmn = mul2(HTmp, qvd);   // (-hq,  hq)
        float2 hrn2 = mul2(HTn2, rvd);   // (-hr, -hr)
        float2 hr2  = mul2(HTp2, rvd);   // ( hr,  hr)

        // (-t0, t2) = (-hp,hp)*(q1,q3) + (-hq,hq)*(q2,q0) + (-hr,-hr)*(q3,q1)
        float2 tA = fma2(hrn2, Qas, fma2(hqmn, Qb, mul2(hpmn, Qa)));
        // ( t1, t3) = (hp,-hp)*(q0,q2) + (-hq,hq)*(q3,q1) + (hr,hr)*(q2,q0)
        float2 tB = fma2(hr2,  Qb,  fma2(hqmn, Qas, mul2(hpm, Qbs)));
        float2 nq02 = add2(Qbs, tA);  // (q0 - t0, q2 + t2)
        float2 nq13 = add2(Qa,  tB);  // (q1 + t1, q3 + t3)

        // body rates (coefficients pre-paired & sign-folded in memory)
        float2 qp  = make_float2(qv, pv);
        float2 X1  = mul2(qp, rvd);              // (qv*rv, pv*rv)
        float2 wsd = make_float2(wsum, wsum);
        float2 X2  = mul2(wsd, qp);              // (wq, wp)
        float2 X3  = make_float2(smm, spp);
        float2 r12 = fma2(K, X3, fma2(U, X2, mul2(E, X1)));
        float npv = pv + r12.x;
        float nqv = qv + r12.y;
        float pvqv = pv * qv;
        float r3 = fmaf(nkToz, sqn, e3 * pvqv);
        float nrv = rv + r3;

        float nxz_raw = fmaf(tau, nzd, xz);

        float2 nWa = fma2(TAUD, Da, WaC);
        float2 nWb = fma2(TAUD, Db, WbC);
        float2 nDa = fma2(TAUD, wddA, Da);
        float2 nDb = fma2(TAUD, wddB, Db);

        // |diff|<=400 is false for NaN/Inf diff; xz always finite
        float diff = nxz_raw - xz;
        float nxz = (fabsf(diff) <= 400.0f) ? nxz_raw : xz;

        float dz = nxz - lbl;
        accf = fmaf(dz, dz, accf);

        xz = nxz; zd = nzd;
        q0 = nq02.x; q2 = nq02.y; q1 = nq13.x; q3 = nq13.y;
        pv = npv; qv = nqv; rv = nrv;
        Wa = nWa; Wb = nWb; Da = nDa; Db = nDb;
    };

    #define LOADS(ii, slot) { \
        const float4* p = base + (size_t)(ii) * STRIDE; \
        buf[slot][0] = p[0]; buf[slot][1] = p[1]; buf[slot][2] = p[2]; \
        buf[slot][3] = p[3]; buf[slot][4] = p[4]; }
    #define STEP(slot) step(buf[slot][0], buf[slot][1], buf[slot][2], \
                            buf[slot][3], buf[slot][4]);

    for (int i = 0; i < 4092; i += 6) {
        STEP(0) LOADS(i + 6,  0)
        STEP(1) LOADS(i + 7,  1)
        STEP(2) LOADS(i + 8,  2)
        STEP(3) LOADS(i + 9,  3)
        STEP(4) LOADS(i + 10, 4)
        STEP(5) LOADS(i + 11, 5)
        acc += (double)accf;
        accf = 0.f;
    }
    STEP(0)
    STEP(1)
    STEP(2)
    acc += (double)accf;

    #undef LOADS
    #undef STEP

    g_loss[b] = acc;
}

// ---------------------------------------------------------------------------
// Kernel 4: deterministic loss reduction -> mean
// ---------------------------------------------------------------------------
__global__ void loss_kernel(float* __restrict__ out)
{
    __shared__ double red[B_DIM];
    red[threadIdx.x] = g_loss[threadIdx.x];
    __syncthreads();
    #pragma unroll
    for (int s = 256; s > 0; s >>= 1) {
        if (threadIdx.x < s) red[threadIdx.x] += red[threadIdx.x + s];
        __syncthreads();
    }
    if (threadIdx.x == 0) out[0] = (float)(red[0] / (double)NELEM);
}

// ---------------------------------------------------------------------------
// Launch
// ---------------------------------------------------------------------------
extern "C" void kernel_launch(void* const* d_in, const int* in_sizes, int n_in,
                              void* d_out, int out_size)
{
    const float* labels = (const float*)d_in[0];
    const float* logits = (const float*)d_in[1];
    const float* u1     = (const float*)d_in[2];
    const float* u2     = (const float*)d_in[3];
    const float* u3     = (const float*)d_in[4];
    const float* u4     = (const float*)d_in[5];
    const float* maxM   = (const float*)d_in[6];
    const float* minM   = (const float*)d_in[7];

    prep_kernel<<<PREP_BLOCKS, 256>>>(logits, u1, u2, u3, u4, maxM, minM, labels);
    hover_kernel<<<1, 256>>>();
    sim_kernel<<<16, 32>>>(labels);
    loss_kernel<<<1, B_DIM>>>((float*)d_out);
}